// round 5
// baseline (speedup 1.0000x reference)
#include <cuda_runtime.h>
#include <cuda_bf16.h>

// ---------------------------------------------------------------------------
// Round 5: deeper async pipeline (4-stage cp.async ring, 1 barrier/k-step),
// kv K-split x4 with fp32 partials + merge, launch_bounds(256,1).
// mma.sync.m16n8k16 bf16 split-hi/lo (hh + hl + lh).
// Token permutation t' = m*1024 + w makes every GEMM K-major contiguous.
// ---------------------------------------------------------------------------

typedef unsigned int u32;

// ---------------- device buffers (bf16 hi/lo splits) -----------------------
__device__ __nv_bfloat16 g_Xh[2L * 16384 * 256], g_Xl[2L * 16384 * 256];
__device__ __nv_bfloat16 g_VTh[2L * 256 * 16384], g_VTl[2L * 256 * 16384];
__device__ __nv_bfloat16 g_WkTh[256 * 256], g_WkTl[256 * 256];
__device__ __nv_bfloat16 g_WqTh[256 * 256], g_WqTl[256 * 256];
__device__ __nv_bfloat16 g_PKh[2L * 256 * 16384], g_PKl[2L * 256 * 16384];
__device__ __nv_bfloat16 g_PQh[2L * 1024 * 256], g_PQl[2L * 1024 * 256];
__device__ __nv_bfloat16 g_KVh[2L * 4096 * 256], g_KVl[2L * 4096 * 256];
__device__ float g_KVp[4L * 2 * 4096 * 256];     // 4 K-slices, fp32 partials

// ---------------- smem geometry -------------------------------------------
// One stage = 4 tiles (Ah, Al, Bh, Bl), each 128 rows x 32 bf16, pitch 80B.
#define TILE_B   10240                 // 128 * 80
#define STAGE_B  (4 * TILE_B)          // 40960
#define NSTAGE   4
#define SM_PS    (NSTAGE * STAGE_B)    // scratch after ring
#define SMEM_BYTES (NSTAGE * STAGE_B + 1024)

// ---------------- PTX helpers ---------------------------------------------
__device__ __forceinline__ u32 smem_u32(const void* p) {
    u32 a;
    asm("{ .reg .u64 t; cvta.to.shared.u64 t, %1; cvt.u32.u64 %0, t; }"
        : "=r"(a) : "l"(p));
    return a;
}
__device__ __forceinline__ void cp_async16(u32 dst, const void* src) {
    asm volatile("cp.async.cg.shared.global [%0], [%1], 16;"
                 :: "r"(dst), "l"(src));
}
#define CP_COMMIT() asm volatile("cp.async.commit_group;" ::: "memory")
#define CP_WAIT(n)  asm volatile("cp.async.wait_group %0;" :: "n"(n) : "memory")

__device__ __forceinline__ void ldmx4(u32& r0, u32& r1, u32& r2, u32& r3, u32 a) {
    asm volatile("ldmatrix.sync.aligned.m8n8.x4.shared.b16 {%0,%1,%2,%3}, [%4];"
                 : "=r"(r0), "=r"(r1), "=r"(r2), "=r"(r3) : "r"(a));
}
__device__ __forceinline__ void mma_bf16(float* c, const u32* a, const u32* b) {
    asm volatile(
        "mma.sync.aligned.m16n8k16.row.col.f32.bf16.bf16.f32 "
        "{%0,%1,%2,%3}, {%4,%5,%6,%7}, {%8,%9}, {%0,%1,%2,%3};"
        : "+f"(c[0]), "+f"(c[1]), "+f"(c[2]), "+f"(c[3])
        : "r"(a[0]), "r"(a[1]), "r"(a[2]), "r"(a[3]), "r"(b[0]), "r"(b[1]));
}

__device__ __forceinline__ float phi_act(float z) {
    return z > 0.f ? z + 2.f : __expf(z) + 1.f;
}
__device__ __forceinline__ void split1(float x, __nv_bfloat16& h, __nv_bfloat16& l) {
    h = __float2bfloat16(x);
    l = __float2bfloat16(x - __bfloat162float(h));
}
__device__ __forceinline__ u32 pack_bf2(__nv_bfloat16 a, __nv_bfloat16 b) {
    __nv_bfloat162 p; p.x = a; p.y = b;
    return *(u32*)&p;
}

// ---------------------------------------------------------------------------
// Core mainloop: acc(128x128 f32, per-warp 64x32) += A(128xK) * B(128xK)^T
// with split-bf16 3-term products. K = NB*32. 4-stage cp.async ring.
// ---------------------------------------------------------------------------
__device__ __forceinline__ void run_gemm(
    char* sm, u32 smb,
    const __nv_bfloat16* __restrict__ Ah, const __nv_bfloat16* __restrict__ Al, long sA,
    const __nv_bfloat16* __restrict__ Bh, const __nv_bfloat16* __restrict__ Bl, long sB,
    int NB, float acc[4][4][4])
{
    const int tid = threadIdx.x, wid = tid >> 5, lane = tid & 31;
    const int warp_m = (wid & 1) * 64, warp_n = (wid >> 1) * 32;

    auto issue_stage = [&](int s, int kb) {
        u32 base = smb + s * STAGE_B;
#pragma unroll
        for (int i = 0; i < 8; i++) {
            int ch = i * 256 + tid;                // 2048 chunks of 16B
            int tile = ch >> 9, row = (ch >> 2) & 127, kc = ch & 3;
            const __nv_bfloat16* gb =
                (tile == 0) ? Ah : (tile == 1) ? Al : (tile == 2) ? Bh : Bl;
            long st = (tile < 2) ? sA : sB;
            cp_async16(base + tile * TILE_B + row * 80 + kc * 16,
                       gb + (long)row * st + (long)kb * 32 + kc * 8);
        }
        CP_COMMIT();
    };

    issue_stage(0, 0);
    if (NB > 1) issue_stage(1, 1);
    if (NB > 2) issue_stage(2, 2);

    for (int kb = 0; kb < NB; kb++) {
        const int rem = NB - 1 - kb;
        if (rem >= 2)      CP_WAIT(2);
        else if (rem == 1) CP_WAIT(1);
        else               CP_WAIT(0);
        __syncthreads();
        // Overwrites stage (kb-1)&3 which all warps finished last iteration.
        if (kb + 3 < NB) issue_stage((kb + 3) & 3, kb + 3);

        u32 sb = smb + (kb & 3) * STAGE_B;
        u32 aAddr = sb + (warp_m + (lane & 15)) * 80 + (lane >> 4) * 16;
        u32 bAddr = sb + 2 * TILE_B +
                    (warp_n + (lane & 7) + ((lane >> 4) << 3)) * 80 +
                    ((lane >> 3) & 1) * 16;

#pragma unroll
        for (int kh = 0; kh < 2; kh++) {
            u32 ah[4][4], al[4][4], bh[4][2], bl[4][2];
#pragma unroll
            for (int i = 0; i < 4; i++) {
                ldmx4(ah[i][0], ah[i][1], ah[i][2], ah[i][3],
                      aAddr + i * 16 * 80 + kh * 32);
                ldmx4(al[i][0], al[i][1], al[i][2], al[i][3],
                      aAddr + TILE_B + i * 16 * 80 + kh * 32);
            }
#pragma unroll
            for (int j = 0; j < 2; j++) {
                ldmx4(bh[2 * j][0], bh[2 * j][1], bh[2 * j + 1][0], bh[2 * j + 1][1],
                      bAddr + j * 16 * 80 + kh * 32);
                ldmx4(bl[2 * j][0], bl[2 * j][1], bl[2 * j + 1][0], bl[2 * j + 1][1],
                      bAddr + TILE_B + j * 16 * 80 + kh * 32);
            }
#pragma unroll
            for (int i = 0; i < 4; i++)
#pragma unroll
                for (int j = 0; j < 4; j++) {
                    mma_bf16(acc[i][j], ah[i], bh[j]);
                    mma_bf16(acc[i][j], ah[i], bl[j]);
                    mma_bf16(acc[i][j], al[i], bh[j]);
                }
        }
    }
    __syncthreads();   // protect smem before epilogue staging reuses it
}

// Store per-warp accumulators into Cs[128][132] f32 (reuses stage memory).
__device__ __forceinline__ void stage_C(char* sm, float acc[4][4][4])
{
    const int tid = threadIdx.x, wid = tid >> 5, lane = tid & 31;
    const int warp_m = (wid & 1) * 64, warp_n = (wid >> 1) * 32;
    float* Cs = (float*)sm;
#pragma unroll
    for (int i = 0; i < 4; i++)
#pragma unroll
        for (int j = 0; j < 4; j++) {
            int r = warp_m + i * 16 + (lane >> 2);
            int c = warp_n + j * 8 + (lane & 3) * 2;
            *(float2*)&Cs[r * 132 + c] =
                make_float2(acc[i][j][0], acc[i][j][1]);
            *(float2*)&Cs[(r + 8) * 132 + c] =
                make_float2(acc[i][j][2], acc[i][j][3]);
        }
    __syncthreads();
}

#define ACC_DECL() float acc[4][4][4];                                   \
    _Pragma("unroll") for (int i = 0; i < 4; i++)                        \
    _Pragma("unroll") for (int j = 0; j < 4; j++)                        \
    _Pragma("unroll") for (int e = 0; e < 4; e++) acc[i][j][e] = 0.f;

// ---------------------------------------------------------------------------
// proj kernel: blockIdx.x<256 -> K-projection (M=c, N=tokens),
//              else            -> Q-projection (M=r, N=c).  K=256 (NB=8).
// ---------------------------------------------------------------------------
__global__ __launch_bounds__(256, 1) void proj_kernel(
    const float* __restrict__ bk, const float* __restrict__ bq)
{
    extern __shared__ char sm[];
    u32 smb = smem_u32(sm);
    const int tid = threadIdx.x;
    const int b = blockIdx.y;
    const bool isK = blockIdx.x < 256;
    int c0, t0 = 0, r0 = 0;
    const __nv_bfloat16 *Ah, *Al, *Bh, *Bl;
    if (isK) {
        c0 = (blockIdx.x >> 7) * 128;
        t0 = (blockIdx.x & 127) * 128;
        Ah = g_WkTh + c0 * 256;  Al = g_WkTl + c0 * 256;
        Bh = g_Xh + ((long)b * 16384 + t0) * 256;
        Bl = g_Xl + ((long)b * 16384 + t0) * 256;
    } else {
        int xi = blockIdx.x - 256;
        r0 = (xi >> 1) * 128;
        c0 = (xi & 1) * 128;
        Ah = g_Xh + ((long)b * 16384 + r0) * 256;
        Al = g_Xl + ((long)b * 16384 + r0) * 256;
        Bh = g_WqTh + c0 * 256;  Bl = g_WqTl + c0 * 256;
    }

    ACC_DECL();
    run_gemm(sm, smb, Ah, Al, 256, Bh, Bl, 256, 8, acc);
    stage_C(sm, acc);
    const float* Cs = (const float*)sm;

    if (isK) {
        const int w0 = t0 >> 4;   // 8 windows in this token tile
#pragma unroll
        for (int it = 0; it < 8; it++) {
            int task = it * 256 + tid;            // 2048 = 128 c x 16 m
            int c = task >> 4, m = task & 15;
            float bias = bk[c0 + c];
            u32 H[4], L[4];
#pragma unroll
            for (int wl = 0; wl < 4; wl++) {
                float x0 = phi_act(Cs[c * 132 + (2 * wl) * 16 + m] + bias);
                float x1 = phi_act(Cs[c * 132 + (2 * wl + 1) * 16 + m] + bias);
                __nv_bfloat16 h0, l0, h1, l1;
                split1(x0, h0, l0); split1(x1, h1, l1);
                H[wl] = pack_bf2(h0, h1); L[wl] = pack_bf2(l0, l1);
            }
            long off = ((long)b * 256 + c0 + c) * 16384 + m * 1024 + w0;
            *(uint4*)(g_PKh + off) = make_uint4(H[0], H[1], H[2], H[3]);
            *(uint4*)(g_PKl + off) = make_uint4(L[0], L[1], L[2], L[3]);
        }
    } else {
#pragma unroll
        for (int it = 0; it < 8; it++) {
            int task = it * 256 + tid;            // 2048 = 128 r x 16 chunks
            int r = task >> 4, ch = task & 15;
            u32 H[4], L[4];
#pragma unroll
            for (int p = 0; p < 4; p++) {
                int col = ch * 8 + 2 * p;
                float x0 = phi_act(Cs[r * 132 + col] + bq[c0 + col]);
                float x1 = phi_act(Cs[r * 132 + col + 1] + bq[c0 + col + 1]);
                __nv_bfloat16 h0, l0, h1, l1;
                split1(x0, h0, l0); split1(x1, h1, l1);
                H[p] = pack_bf2(h0, h1); L[p] = pack_bf2(l0, l1);
            }
            long off = ((long)b * 1024 + r0 + r) * 256 + c0 + ch * 8;
            *(uint4*)(g_PQh + off) = make_uint4(H[0], H[1], H[2], H[3]);
            *(uint4*)(g_PQl + off) = make_uint4(L[0], L[1], L[2], L[3]);
        }
    }
}

// ---------------------------------------------------------------------------
// kv kernel (partial): one 256-token K-slice of
// KVT[b][m*256+d][c] = sum_{t'} VT[d][t'] phiKT[c][t'].
// grid (dtile=2, ctile=2, slice*32 + b*16 + m), NB=8. fp32 partial output.
// ---------------------------------------------------------------------------
__global__ __launch_bounds__(256, 1) void kv_kernel()
{
    extern __shared__ char sm[];
    u32 smb = smem_u32(sm);
    const int tid = threadIdx.x;
    const int zz = blockIdx.z;
    const int slice = zz >> 5, bm = zz & 31;
    const int b = bm >> 4, m = bm & 15;
    const int d0 = blockIdx.x * 128, c0 = blockIdx.y * 128;
    const long abase = ((long)b * 256 + d0) * 16384 + m * 1024 + slice * 256;
    const long bbase = ((long)b * 256 + c0) * 16384 + m * 1024 + slice * 256;

    ACC_DECL();
    run_gemm(sm, smb, g_VTh + abase, g_VTl + abase, 16384,
             g_PKh + bbase, g_PKl + bbase, 16384, 8, acc);
    stage_C(sm, acc);
    const float* Cs = (const float*)sm;

    float* dstS = g_KVp + (long)slice * (2L * 4096 * 256);
#pragma unroll
    for (int it = 0; it < 8; it++) {
        int task = it * 256 + tid;                // 2048 = 128 d x 16 chunks
        int d = task >> 4, ch = task & 15;
        float* dst = dstS + ((long)b * 4096 + m * 256 + d0 + d) * 256 + c0 + ch * 8;
        *(float4*)(dst)     = *(const float4*)&Cs[d * 132 + ch * 8];
        *(float4*)(dst + 4) = *(const float4*)&Cs[d * 132 + ch * 8 + 4];
    }
}

// ---------------------------------------------------------------------------
// kv merge: sum 4 fp32 slices, split to bf16 hi/lo. 2M elements.
// ---------------------------------------------------------------------------
__global__ __launch_bounds__(256) void kv_merge_kernel()
{
    const long S = 2L * 4096 * 256;
    long i = (long)blockIdx.x * 256 + threadIdx.x;   // float4 index
    float4 a0 = ((const float4*)g_KVp)[i];
    float4 a1 = ((const float4*)(g_KVp + S))[i];
    float4 a2 = ((const float4*)(g_KVp + 2 * S))[i];
    float4 a3 = ((const float4*)(g_KVp + 3 * S))[i];
    float f[4] = { (a0.x + a1.x) + (a2.x + a3.x),
                   (a0.y + a1.y) + (a2.y + a3.y),
                   (a0.z + a1.z) + (a2.z + a3.z),
                   (a0.w + a1.w) + (a2.w + a3.w) };
    __nv_bfloat16 h0, l0, h1, l1, h2, l2, h3, l3;
    split1(f[0], h0, l0); split1(f[1], h1, l1);
    split1(f[2], h2, l2); split1(f[3], h3, l3);
    ((uint2*)g_KVh)[i] = make_uint2(pack_bf2(h0, h1), pack_bf2(h2, h3));
    ((uint2*)g_KVl)[i] = make_uint2(pack_bf2(l0, l1), pack_bf2(l2, l3));
}

// ---------------------------------------------------------------------------
// att kernel: out[b][w*256+n*16+m][d] = sum_c phiQ[r][c] KVT[m*256+d][c] + p.
// grid (rtile=8, jtile=32, b). K=256 (NB=8).
// ---------------------------------------------------------------------------
__global__ __launch_bounds__(256, 1) void att_kernel(
    const float* __restrict__ embed, const float* __restrict__ Wp,
    const float* __restrict__ bp, float* __restrict__ out)
{
    extern __shared__ char sm[];
    u32 smb = smem_u32(sm);
    const int tid = threadIdx.x;
    const int b = blockIdx.z;
    const int r0 = blockIdx.x * 128;
    const int j0 = blockIdx.y * 128;
    const int m = j0 >> 8, d0 = j0 & 255;
    const long abase = ((long)b * 1024 + r0) * 256;
    const long bbase = ((long)b * 4096 + j0) * 256;

    if (tid < 128) {
        int r = r0 + tid, w = r >> 4, n = r & 15;
        const float* e = embed + ((((long)b * 1024 + w) * 16 + n) * 16 + m) * 3;
        ((float*)(sm + SM_PS))[tid] =
            e[0] * Wp[0] + e[1] * Wp[1] + e[2] * Wp[2] + bp[0];
    }

    ACC_DECL();
    run_gemm(sm, smb, g_PQh + abase, g_PQl + abase, 256,
             g_KVh + bbase, g_KVl + bbase, 256, 8, acc);
    stage_C(sm, acc);
    const float* Cs = (const float*)sm;

#pragma unroll
    for (int it = 0; it < 16; it++) {
        int task = it * 256 + tid;                // 4096 = 128 r x 32 f4-chunks
        int r = task >> 5, ch = task & 31;
        float4 v = *(const float4*)&Cs[r * 132 + ch * 4];
        float p = ((const float*)(sm + SM_PS))[r];
        v.x += p; v.y += p; v.z += p; v.w += p;
        int rg = r0 + r, w = rg >> 4, n = rg & 15;
        long t = (long)w * 256 + n * 16 + m;
        *(float4*)(out + ((long)b * 16384 + t) * 256 + d0 + ch * 4) = v;
    }
}

// ---------------------------------------------------------------------------
// prep kernels
// ---------------------------------------------------------------------------
__global__ __launch_bounds__(256) void prep_split(const float* __restrict__ X)
{
    long i = (long)blockIdx.x * 256 + threadIdx.x;   // float4 index
    float4 v = ((const float4*)X)[i];
    __nv_bfloat16 h0, l0, h1, l1, h2, l2, h3, l3;
    split1(v.x, h0, l0); split1(v.y, h1, l1);
    split1(v.z, h2, l2); split1(v.w, h3, l3);
    ((uint2*)g_Xh)[i] = make_uint2(pack_bf2(h0, h1), pack_bf2(h2, h3));
    ((uint2*)g_Xl)[i] = make_uint2(pack_bf2(l0, l1), pack_bf2(l2, l3));
}

// VT[b][d][m*1024+w] = X[b][w*16+m][d]; grid (wtile=32, dtile=8, b*16+m)
__global__ __launch_bounds__(256) void prep_vt(const float* __restrict__ X)
{
    __shared__ float tile[32][33];
    const int bm = blockIdx.z, b = bm >> 4, m = bm & 15;
    const int w0 = blockIdx.x * 32, d0 = blockIdx.y * 32;
    const int dx = threadIdx.x & 31, dy = threadIdx.x >> 5;
#pragma unroll
    for (int p = 0; p < 4; p++) {
        int w = w0 + dy + p * 8;
        tile[dy + p * 8][dx] =
            X[((long)b * 16384 + (long)w * 16 + m) * 256 + d0 + dx];
    }
    __syncthreads();
#pragma unroll
    for (int p = 0; p < 4; p++) {
        int d = d0 + dy + p * 8;
        float v = tile[dx][dy + p * 8];
        __nv_bfloat16 h, l; split1(v, h, l);
        long off = ((long)b * 256 + d) * 16384 + m * 1024 + w0 + dx;
        g_VTh[off] = h; g_VTl[off] = l;
    }
}

// WT[n][k] = W[k][n]; grid (ktile=8, ntile=8, 2: 0=Wk,1=Wq)
__global__ __launch_bounds__(256) void prep_w(
    const float* __restrict__ Wk, const float* __restrict__ Wq)
{
    __shared__ float tile[32][33];
    const int isQ = blockIdx.z;
    const float* W = isQ ? Wq : Wk;
    __nv_bfloat16* TH = isQ ? g_WqTh : g_WkTh;
    __nv_bfloat16* TL = isQ ? g_WqTl : g_WkTl;
    const int k0 = blockIdx.x * 32, n0 = blockIdx.y * 32;
    const int dx = threadIdx.x & 31, dy = threadIdx.x >> 5;
#pragma unroll
    for (int p = 0; p < 4; p++)
        tile[dy + p * 8][dx] = W[(k0 + dy + p * 8) * 256 + n0 + dx];
    __syncthreads();
#pragma unroll
    for (int p = 0; p < 4; p++) {
        float v = tile[dx][dy + p * 8];
        __nv_bfloat16 h, l; split1(v, h, l);
        int off = (n0 + dy + p * 8) * 256 + k0 + dx;
        TH[off] = h; TL[off] = l;
    }
}

// ---------------------------------------------------------------------------
// Inputs (metadata order): input, embed_qk, Wq, bq, Wk, bk, Wp, bp
// ---------------------------------------------------------------------------
extern "C" void kernel_launch(void* const* d_in, const int* in_sizes, int n_in,
                              void* d_out, int out_size)
{
    const float* input = (const float*)d_in[0];
    const float* embed = (const float*)d_in[1];
    const float* Wq    = (const float*)d_in[2];
    const float* bq    = (const float*)d_in[3];
    const float* Wk    = (const float*)d_in[4];
    const float* bk    = (const float*)d_in[5];
    const float* Wp    = (const float*)d_in[6];
    const float* bp    = (const float*)d_in[7];
    float* out = (float*)d_out;

    cudaFuncSetAttribute(proj_kernel, cudaFuncAttributeMaxDynamicSharedMemorySize, SMEM_BYTES);
    cudaFuncSetAttribute(kv_kernel,   cudaFuncAttributeMaxDynamicSharedMemorySize, SMEM_BYTES);
    cudaFuncSetAttribute(att_kernel,  cudaFuncAttributeMaxDynamicSharedMemorySize, SMEM_BYTES);

    prep_split<<<8192, 256>>>(input);
    prep_vt<<<dim3(32, 8, 32), 256>>>(input);
    prep_w<<<dim3(8, 8, 2), 256>>>(Wk, Wq);

    proj_kernel<<<dim3(272, 2), 256, SMEM_BYTES>>>(bk, bq);
    kv_kernel<<<dim3(2, 2, 128), 256, SMEM_BYTES>>>();
    kv_merge_kernel<<<2048, 256>>>();
    att_kernel<<<dim3(8, 32, 2), 256, SMEM_BYTES>>>(embed, Wp, bp, out);
}

// round 6
// speedup vs baseline: 1.0947x; 1.0947x over previous
#include <cuda_runtime.h>
#include <cuda_bf16.h>

// ---------------------------------------------------------------------------
// Round 6: Round-4 proven core (2-stage cp.async, 83KB smem -> 2 CTAs/SM,
// 128 regs) + kv K-split x4 with fp32 partials/merge + MMA term reordering
// (3 passes hh/hl/lh -> no 3-deep dependent HMMA chains).
// mma.sync.m16n8k16 bf16 split-hi/lo. Token permutation t' = m*1024 + w.
// ---------------------------------------------------------------------------

typedef unsigned int u32;

// ---------------- device buffers (bf16 hi/lo splits) -----------------------
__device__ __nv_bfloat16 g_Xh[2L * 16384 * 256], g_Xl[2L * 16384 * 256];
__device__ __nv_bfloat16 g_VTh[2L * 256 * 16384], g_VTl[2L * 256 * 16384];
__device__ __nv_bfloat16 g_WkTh[256 * 256], g_WkTl[256 * 256];
__device__ __nv_bfloat16 g_WqTh[256 * 256], g_WqTl[256 * 256];
__device__ __nv_bfloat16 g_PKh[2L * 256 * 16384], g_PKl[2L * 256 * 16384];
__device__ __nv_bfloat16 g_PQh[2L * 1024 * 256], g_PQl[2L * 1024 * 256];
__device__ __nv_bfloat16 g_KVh[2L * 4096 * 256], g_KVl[2L * 4096 * 256];
__device__ float g_KVp[4L * 2 * 4096 * 256];     // 4 K-slices, fp32 partials

// ---------------- smem geometry -------------------------------------------
// One stage = 4 tiles (Ah, Al, Bh, Bl), each 128 rows x 32 bf16, pitch 80B.
#define TILE_B   10240                 // 128 * 80
#define STAGE_B  (4 * TILE_B)          // 40960
#define SM_PS    (2 * STAGE_B)         // scratch after both stages
#define SMEM_BYTES (2 * STAGE_B + 1024)   // 83968 -> 2 CTAs/SM

// ---------------- PTX helpers ---------------------------------------------
__device__ __forceinline__ u32 smem_u32(const void* p) {
    u32 a;
    asm("{ .reg .u64 t; cvta.to.shared.u64 t, %1; cvt.u32.u64 %0, t; }"
        : "=r"(a) : "l"(p));
    return a;
}
__device__ __forceinline__ void cp_async16(u32 dst, const void* src) {
    asm volatile("cp.async.cg.shared.global [%0], [%1], 16;"
                 :: "r"(dst), "l"(src));
}
#define CP_COMMIT() asm volatile("cp.async.commit_group;" ::: "memory")
#define CP_WAIT(n)  asm volatile("cp.async.wait_group %0;" :: "n"(n) : "memory")

__device__ __forceinline__ void ldmx4(u32& r0, u32& r1, u32& r2, u32& r3, u32 a) {
    asm volatile("ldmatrix.sync.aligned.m8n8.x4.shared.b16 {%0,%1,%2,%3}, [%4];"
                 : "=r"(r0), "=r"(r1), "=r"(r2), "=r"(r3) : "r"(a));
}
__device__ __forceinline__ void mma_bf16(float* c, const u32* a, const u32* b) {
    asm volatile(
        "mma.sync.aligned.m16n8k16.row.col.f32.bf16.bf16.f32 "
        "{%0,%1,%2,%3}, {%4,%5,%6,%7}, {%8,%9}, {%0,%1,%2,%3};"
        : "+f"(c[0]), "+f"(c[1]), "+f"(c[2]), "+f"(c[3])
        : "r"(a[0]), "r"(a[1]), "r"(a[2]), "r"(a[3]), "r"(b[0]), "r"(b[1]));
}

__device__ __forceinline__ float phi_act(float z) {
    return z > 0.f ? z + 2.f : __expf(z) + 1.f;
}
__device__ __forceinline__ void split1(float x, __nv_bfloat16& h, __nv_bfloat16& l) {
    h = __float2bfloat16(x);
    l = __float2bfloat16(x - __bfloat162float(h));
}
__device__ __forceinline__ u32 pack_bf2(__nv_bfloat16 a, __nv_bfloat16 b) {
    __nv_bfloat162 p; p.x = a; p.y = b;
    return *(u32*)&p;
}

// ---------------------------------------------------------------------------
// Core mainloop: acc(128x128 f32, per-warp 64x32) += A(128xK) * B(128xK)^T
// with split-bf16 3-term products. K = NB*32. 2-stage double buffer.
// MMA terms issued in 3 passes (hh, hl, lh) so each accumulator's reuses are
// separated by 15 independent MMAs.
// ---------------------------------------------------------------------------
__device__ __forceinline__ void run_gemm(
    char* sm, u32 smb,
    const __nv_bfloat16* __restrict__ Ah, const __nv_bfloat16* __restrict__ Al, long sA,
    const __nv_bfloat16* __restrict__ Bh, const __nv_bfloat16* __restrict__ Bl, long sB,
    int NB, float acc[4][4][4])
{
    const int tid = threadIdx.x, wid = tid >> 5, lane = tid & 31;
    const int warp_m = (wid & 1) * 64, warp_n = (wid >> 1) * 32;

    auto issue_stage = [&](int s, int kb) {
        u32 base = smb + s * STAGE_B;
#pragma unroll
        for (int i = 0; i < 8; i++) {
            int ch = i * 256 + tid;                // 2048 chunks of 16B
            int tile = ch >> 9, row = (ch >> 2) & 127, kc = ch & 3;
            const __nv_bfloat16* gb =
                (tile == 0) ? Ah : (tile == 1) ? Al : (tile == 2) ? Bh : Bl;
            long st = (tile < 2) ? sA : sB;
            cp_async16(base + tile * TILE_B + row * 80 + kc * 16,
                       gb + (long)row * st + (long)kb * 32 + kc * 8);
        }
        CP_COMMIT();
    };

    issue_stage(0, 0);

    for (int kb = 0; kb < NB; kb++) {
        if (kb + 1 < NB) { issue_stage((kb + 1) & 1, kb + 1); CP_WAIT(1); }
        else             { CP_WAIT(0); }
        __syncthreads();

        u32 sb = smb + (kb & 1) * STAGE_B;
        u32 aAddr = sb + (warp_m + (lane & 15)) * 80 + (lane >> 4) * 16;
        u32 bAddr = sb + 2 * TILE_B +
                    (warp_n + (lane & 7) + ((lane >> 4) << 3)) * 80 +
                    ((lane >> 3) & 1) * 16;

#pragma unroll
        for (int kh = 0; kh < 2; kh++) {
            u32 ah[4][4], al[4][4], bh[4][2], bl[4][2];
#pragma unroll
            for (int i = 0; i < 4; i++) {
                ldmx4(ah[i][0], ah[i][1], ah[i][2], ah[i][3],
                      aAddr + i * 16 * 80 + kh * 32);
                ldmx4(al[i][0], al[i][1], al[i][2], al[i][3],
                      aAddr + TILE_B + i * 16 * 80 + kh * 32);
            }
#pragma unroll
            for (int j = 0; j < 2; j++) {
                ldmx4(bh[2 * j][0], bh[2 * j][1], bh[2 * j + 1][0], bh[2 * j + 1][1],
                      bAddr + j * 16 * 80 + kh * 32);
                ldmx4(bl[2 * j][0], bl[2 * j][1], bl[2 * j + 1][0], bl[2 * j + 1][1],
                      bAddr + TILE_B + j * 16 * 80 + kh * 32);
            }
            // pass 1: hh
#pragma unroll
            for (int i = 0; i < 4; i++)
#pragma unroll
                for (int j = 0; j < 4; j++)
                    mma_bf16(acc[i][j], ah[i], bh[j]);
            // pass 2: hl
#pragma unroll
            for (int i = 0; i < 4; i++)
#pragma unroll
                for (int j = 0; j < 4; j++)
                    mma_bf16(acc[i][j], ah[i], bl[j]);
            // pass 3: lh
#pragma unroll
            for (int i = 0; i < 4; i++)
#pragma unroll
                for (int j = 0; j < 4; j++)
                    mma_bf16(acc[i][j], al[i], bh[j]);
        }
        __syncthreads();
    }
}

// Store per-warp accumulators into Cs[128][132] f32 (reuses stage memory).
__device__ __forceinline__ void stage_C(char* sm, float acc[4][4][4])
{
    const int tid = threadIdx.x, wid = tid >> 5, lane = tid & 31;
    const int warp_m = (wid & 1) * 64, warp_n = (wid >> 1) * 32;
    float* Cs = (float*)sm;
#pragma unroll
    for (int i = 0; i < 4; i++)
#pragma unroll
        for (int j = 0; j < 4; j++) {
            int r = warp_m + i * 16 + (lane >> 2);
            int c = warp_n + j * 8 + (lane & 3) * 2;
            *(float2*)&Cs[r * 132 + c] =
                make_float2(acc[i][j][0], acc[i][j][1]);
            *(float2*)&Cs[(r + 8) * 132 + c] =
                make_float2(acc[i][j][2], acc[i][j][3]);
        }
    __syncthreads();
}

#define ACC_DECL() float acc[4][4][4];                                   \
    _Pragma("unroll") for (int i = 0; i < 4; i++)                        \
    _Pragma("unroll") for (int j = 0; j < 4; j++)                        \
    _Pragma("unroll") for (int e = 0; e < 4; e++) acc[i][j][e] = 0.f;

// ---------------------------------------------------------------------------
// proj kernel: blockIdx.x<256 -> K-projection (M=c, N=tokens),
//              else            -> Q-projection (M=r, N=c).  K=256 (NB=8).
// ---------------------------------------------------------------------------
__global__ __launch_bounds__(256) void proj_kernel(
    const float* __restrict__ bk, const float* __restrict__ bq)
{
    extern __shared__ char sm[];
    u32 smb = smem_u32(sm);
    const int tid = threadIdx.x;
    const int b = blockIdx.y;
    const bool isK = blockIdx.x < 256;
    int c0, t0 = 0, r0 = 0;
    const __nv_bfloat16 *Ah, *Al, *Bh, *Bl;
    if (isK) {
        c0 = (blockIdx.x >> 7) * 128;
        t0 = (blockIdx.x & 127) * 128;
        Ah = g_WkTh + c0 * 256;  Al = g_WkTl + c0 * 256;
        Bh = g_Xh + ((long)b * 16384 + t0) * 256;
        Bl = g_Xl + ((long)b * 16384 + t0) * 256;
    } else {
        int xi = blockIdx.x - 256;
        r0 = (xi >> 1) * 128;
        c0 = (xi & 1) * 128;
        Ah = g_Xh + ((long)b * 16384 + r0) * 256;
        Al = g_Xl + ((long)b * 16384 + r0) * 256;
        Bh = g_WqTh + c0 * 256;  Bl = g_WqTl + c0 * 256;
    }

    ACC_DECL();
    run_gemm(sm, smb, Ah, Al, 256, Bh, Bl, 256, 8, acc);
    stage_C(sm, acc);
    const float* Cs = (const float*)sm;

    if (isK) {
        const int w0 = t0 >> 4;   // 8 windows in this token tile
#pragma unroll
        for (int it = 0; it < 8; it++) {
            int task = it * 256 + tid;            // 2048 = 128 c x 16 m
            int c = task >> 4, m = task & 15;
            float bias = bk[c0 + c];
            u32 H[4], L[4];
#pragma unroll
            for (int wl = 0; wl < 4; wl++) {
                float x0 = phi_act(Cs[c * 132 + (2 * wl) * 16 + m] + bias);
                float x1 = phi_act(Cs[c * 132 + (2 * wl + 1) * 16 + m] + bias);
                __nv_bfloat16 h0, l0, h1, l1;
                split1(x0, h0, l0); split1(x1, h1, l1);
                H[wl] = pack_bf2(h0, h1); L[wl] = pack_bf2(l0, l1);
            }
            long off = ((long)b * 256 + c0 + c) * 16384 + m * 1024 + w0;
            *(uint4*)(g_PKh + off) = make_uint4(H[0], H[1], H[2], H[3]);
            *(uint4*)(g_PKl + off) = make_uint4(L[0], L[1], L[2], L[3]);
        }
    } else {
#pragma unroll
        for (int it = 0; it < 8; it++) {
            int task = it * 256 + tid;            // 2048 = 128 r x 16 chunks
            int r = task >> 4, ch = task & 15;
            u32 H[4], L[4];
#pragma unroll
            for (int p = 0; p < 4; p++) {
                int col = ch * 8 + 2 * p;
                float x0 = phi_act(Cs[r * 132 + col] + bq[c0 + col]);
                float x1 = phi_act(Cs[r * 132 + col + 1] + bq[c0 + col + 1]);
                __nv_bfloat16 h0, l0, h1, l1;
                split1(x0, h0, l0); split1(x1, h1, l1);
                H[p] = pack_bf2(h0, h1); L[p] = pack_bf2(l0, l1);
            }
            long off = ((long)b * 1024 + r0 + r) * 256 + c0 + ch * 8;
            *(uint4*)(g_PQh + off) = make_uint4(H[0], H[1], H[2], H[3]);
            *(uint4*)(g_PQl + off) = make_uint4(L[0], L[1], L[2], L[3]);
        }
    }
}

// ---------------------------------------------------------------------------
// kv kernel (partial): one 256-token K-slice of
// KVT[b][m*256+d][c] = sum_{t'} VT[d][t'] phiKT[c][t'].
// grid (dtile=2, ctile=2, slice*32 + b*16 + m), NB=8. fp32 partial output.
// ---------------------------------------------------------------------------
__global__ __launch_bounds__(256) void kv_kernel()
{
    extern __shared__ char sm[];
    u32 smb = smem_u32(sm);
    const int tid = threadIdx.x;
    const int zz = blockIdx.z;
    const int slice = zz >> 5, bm = zz & 31;
    const int b = bm >> 4, m = bm & 15;
    const int d0 = blockIdx.x * 128, c0 = blockIdx.y * 128;
    const long abase = ((long)b * 256 + d0) * 16384 + m * 1024 + slice * 256;
    const long bbase = ((long)b * 256 + c0) * 16384 + m * 1024 + slice * 256;

    ACC_DECL();
    run_gemm(sm, smb, g_VTh + abase, g_VTl + abase, 16384,
             g_PKh + bbase, g_PKl + bbase, 16384, 8, acc);
    stage_C(sm, acc);
    const float* Cs = (const float*)sm;

    float* dstS = g_KVp + (long)slice * (2L * 4096 * 256);
#pragma unroll
    for (int it = 0; it < 8; it++) {
        int task = it * 256 + tid;                // 2048 = 128 d x 16 chunks
        int d = task >> 4, ch = task & 15;
        float* dst = dstS + ((long)b * 4096 + m * 256 + d0 + d) * 256 + c0 + ch * 8;
        *(float4*)(dst)     = *(const float4*)&Cs[d * 132 + ch * 8];
        *(float4*)(dst + 4) = *(const float4*)&Cs[d * 132 + ch * 8 + 4];
    }
}

// ---------------------------------------------------------------------------
// kv merge: sum 4 fp32 slices, split to bf16 hi/lo. 2M elements.
// ---------------------------------------------------------------------------
__global__ __launch_bounds__(256) void kv_merge_kernel()
{
    const long S = 2L * 4096 * 256;
    long i = (long)blockIdx.x * 256 + threadIdx.x;   // float4 index
    float4 a0 = ((const float4*)g_KVp)[i];
    float4 a1 = ((const float4*)(g_KVp + S))[i];
    float4 a2 = ((const float4*)(g_KVp + 2 * S))[i];
    float4 a3 = ((const float4*)(g_KVp + 3 * S))[i];
    float f[4] = { (a0.x + a1.x) + (a2.x + a3.x),
                   (a0.y + a1.y) + (a2.y + a3.y),
                   (a0.z + a1.z) + (a2.z + a3.z),
                   (a0.w + a1.w) + (a2.w + a3.w) };
    __nv_bfloat16 h0, l0, h1, l1, h2, l2, h3, l3;
    split1(f[0], h0, l0); split1(f[1], h1, l1);
    split1(f[2], h2, l2); split1(f[3], h3, l3);
    ((uint2*)g_KVh)[i] = make_uint2(pack_bf2(h0, h1), pack_bf2(h2, h3));
    ((uint2*)g_KVl)[i] = make_uint2(pack_bf2(l0, l1), pack_bf2(l2, l3));
}

// ---------------------------------------------------------------------------
// att kernel: out[b][w*256+n*16+m][d] = sum_c phiQ[r][c] KVT[m*256+d][c] + p.
// grid (rtile=8, jtile=32, b). K=256 (NB=8).
// ---------------------------------------------------------------------------
__global__ __launch_bounds__(256) void att_kernel(
    const float* __restrict__ embed, const float* __restrict__ Wp,
    const float* __restrict__ bp, float* __restrict__ out)
{
    extern __shared__ char sm[];
    u32 smb = smem_u32(sm);
    const int tid = threadIdx.x;
    const int b = blockIdx.z;
    const int r0 = blockIdx.x * 128;
    const int j0 = blockIdx.y * 128;
    const int m = j0 >> 8, d0 = j0 & 255;
    const long abase = ((long)b * 1024 + r0) * 256;
    const long bbase = ((long)b * 4096 + j0) * 256;

    if (tid < 128) {
        int r = r0 + tid, w = r >> 4, n = r & 15;
        const float* e = embed + ((((long)b * 1024 + w) * 16 + n) * 16 + m) * 3;
        ((float*)(sm + SM_PS))[tid] =
            e[0] * Wp[0] + e[1] * Wp[1] + e[2] * Wp[2] + bp[0];
    }

    ACC_DECL();
    run_gemm(sm, smb, g_PQh + abase, g_PQl + abase, 256,
             g_KVh + bbase, g_KVl + bbase, 256, 8, acc);
    stage_C(sm, acc);
    const float* Cs = (const float*)sm;

#pragma unroll
    for (int it = 0; it < 16; it++) {
        int task = it * 256 + tid;                // 4096 = 128 r x 32 f4-chunks
        int r = task >> 5, ch = task & 31;
        float4 v = *(const float4*)&Cs[r * 132 + ch * 4];
        float p = ((const float*)(sm + SM_PS))[r];
        v.x += p; v.y += p; v.z += p; v.w += p;
        int rg = r0 + r, w = rg >> 4, n = rg & 15;
        long t = (long)w * 256 + n * 16 + m;
        *(float4*)(out + ((long)b * 16384 + t) * 256 + d0 + ch * 4) = v;
    }
}

// ---------------------------------------------------------------------------
// prep kernels
// ---------------------------------------------------------------------------
__global__ __launch_bounds__(256) void prep_split(const float* __restrict__ X)
{
    long i = (long)blockIdx.x * 256 + threadIdx.x;   // float4 index
    float4 v = ((const float4*)X)[i];
    __nv_bfloat16 h0, l0, h1, l1, h2, l2, h3, l3;
    split1(v.x, h0, l0); split1(v.y, h1, l1);
    split1(v.z, h2, l2); split1(v.w, h3, l3);
    ((uint2*)g_Xh)[i] = make_uint2(pack_bf2(h0, h1), pack_bf2(h2, h3));
    ((uint2*)g_Xl)[i] = make_uint2(pack_bf2(l0, l1), pack_bf2(l2, l3));
}

// VT[b][d][m*1024+w] = X[b][w*16+m][d]; grid (wtile=32, dtile=8, b*16+m)
__global__ __launch_bounds__(256) void prep_vt(const float* __restrict__ X)
{
    __shared__ float tile[32][33];
    const int bm = blockIdx.z, b = bm >> 4, m = bm & 15;
    const int w0 = blockIdx.x * 32, d0 = blockIdx.y * 32;
    const int dx = threadIdx.x & 31, dy = threadIdx.x >> 5;
#pragma unroll
    for (int p = 0; p < 4; p++) {
        int w = w0 + dy + p * 8;
        tile[dy + p * 8][dx] =
            X[((long)b * 16384 + (long)w * 16 + m) * 256 + d0 + dx];
    }
    __syncthreads();
#pragma unroll
    for (int p = 0; p < 4; p++) {
        int d = d0 + dy + p * 8;
        float v = tile[dx][dy + p * 8];
        __nv_bfloat16 h, l; split1(v, h, l);
        long off = ((long)b * 256 + d) * 16384 + m * 1024 + w0 + dx;
        g_VTh[off] = h; g_VTl[off] = l;
    }
}

// WT[n][k] = W[k][n]; grid (ktile=8, ntile=8, 2: 0=Wk,1=Wq)
__global__ __launch_bounds__(256) void prep_w(
    const float* __restrict__ Wk, const float* __restrict__ Wq)
{
    __shared__ float tile[32][33];
    const int isQ = blockIdx.z;
    const float* W = isQ ? Wq : Wk;
    __nv_bfloat16* TH = isQ ? g_WqTh : g_WkTh;
    __nv_bfloat16* TL = isQ ? g_WqTl : g_WkTl;
    const int k0 = blockIdx.x * 32, n0 = blockIdx.y * 32;
    const int dx = threadIdx.x & 31, dy = threadIdx.x >> 5;
#pragma unroll
    for (int p = 0; p < 4; p++)
        tile[dy + p * 8][dx] = W[(k0 + dy + p * 8) * 256 + n0 + dx];
    __syncthreads();
#pragma unroll
    for (int p = 0; p < 4; p++) {
        float v = tile[dx][dy + p * 8];
        __nv_bfloat16 h, l; split1(v, h, l);
        int off = (n0 + dy + p * 8) * 256 + k0 + dx;
        TH[off] = h; TL[off] = l;
    }
}

// ---------------------------------------------------------------------------
// Inputs (metadata order): input, embed_qk, Wq, bq, Wk, bk, Wp, bp
// ---------------------------------------------------------------------------
extern "C" void kernel_launch(void* const* d_in, const int* in_sizes, int n_in,
                              void* d_out, int out_size)
{
    const float* input = (const float*)d_in[0];
    const float* embed = (const float*)d_in[1];
    const float* Wq    = (const float*)d_in[2];
    const float* bq    = (const float*)d_in[3];
    const float* Wk    = (const float*)d_in[4];
    const float* bk    = (const float*)d_in[5];
    const float* Wp    = (const float*)d_in[6];
    const float* bp    = (const float*)d_in[7];
    float* out = (float*)d_out;

    cudaFuncSetAttribute(proj_kernel, cudaFuncAttributeMaxDynamicSharedMemorySize, SMEM_BYTES);
    cudaFuncSetAttribute(kv_kernel,   cudaFuncAttributeMaxDynamicSharedMemorySize, SMEM_BYTES);
    cudaFuncSetAttribute(att_kernel,  cudaFuncAttributeMaxDynamicSharedMemorySize, SMEM_BYTES);

    prep_split<<<8192, 256>>>(input);
    prep_vt<<<dim3(32, 8, 32), 256>>>(input);
    prep_w<<<dim3(8, 8, 2), 256>>>(Wk, Wq);

    proj_kernel<<<dim3(272, 2), 256, SMEM_BYTES>>>(bk, bq);
    kv_kernel<<<dim3(2, 2, 128), 256, SMEM_BYTES>>>();
    kv_merge_kernel<<<2048, 256>>>();
    att_kernel<<<dim3(8, 32, 2), 256, SMEM_BYTES>>>(embed, Wp, bp, out);
}

// round 7
// speedup vs baseline: 1.1005x; 1.0053x over previous
#include <cuda_runtime.h>
#include <cuda_bf16.h>

// ---------------------------------------------------------------------------
// Round 7: smem-bandwidth fix. 64x64 warp tiles in 2x2 warp grid (128-thread
// CTAs) -> A/B fragment re-read 2x/2x instead of 4x/2x. 2-stage cp.async,
// 83KB smem -> 2 CTAs/SM. kv K-split x4 (needed for CTA count) + merge.
// mma.sync.m16n8k16 bf16 split-hi/lo (hh+hl+lh). t' = m*1024 + w.
// ---------------------------------------------------------------------------

typedef unsigned int u32;

// ---------------- device buffers (bf16 hi/lo splits) -----------------------
__device__ __nv_bfloat16 g_Xh[2L * 16384 * 256], g_Xl[2L * 16384 * 256];
__device__ __nv_bfloat16 g_VTh[2L * 256 * 16384], g_VTl[2L * 256 * 16384];
__device__ __nv_bfloat16 g_WkTh[256 * 256], g_WkTl[256 * 256];
__device__ __nv_bfloat16 g_WqTh[256 * 256], g_WqTl[256 * 256];
__device__ __nv_bfloat16 g_PKh[2L * 256 * 16384], g_PKl[2L * 256 * 16384];
__device__ __nv_bfloat16 g_PQh[2L * 1024 * 256], g_PQl[2L * 1024 * 256];
__device__ __nv_bfloat16 g_KVh[2L * 4096 * 256], g_KVl[2L * 4096 * 256];
__device__ float g_KVp[4L * 2 * 4096 * 256];     // 4 K-slices, fp32 partials

// ---------------- smem geometry -------------------------------------------
// One stage = 4 tiles (Ah, Al, Bh, Bl), each 128 rows x 32 bf16, pitch 80B.
#define TILE_B   10240                 // 128 * 80
#define STAGE_B  (4 * TILE_B)          // 40960
#define SM_PS    (2 * STAGE_B)         // scratch after both stages
#define SMEM_BYTES (2 * STAGE_B + 1024)   // 83968 -> 2 CTAs/SM

// ---------------- PTX helpers ---------------------------------------------
__device__ __forceinline__ u32 smem_u32(const void* p) {
    u32 a;
    asm("{ .reg .u64 t; cvta.to.shared.u64 t, %1; cvt.u32.u64 %0, t; }"
        : "=r"(a) : "l"(p));
    return a;
}
__device__ __forceinline__ void cp_async16(u32 dst, const void* src) {
    asm volatile("cp.async.cg.shared.global [%0], [%1], 16;"
                 :: "r"(dst), "l"(src));
}
#define CP_COMMIT() asm volatile("cp.async.commit_group;" ::: "memory")
#define CP_WAIT(n)  asm volatile("cp.async.wait_group %0;" :: "n"(n) : "memory")

__device__ __forceinline__ void ldmx4(u32& r0, u32& r1, u32& r2, u32& r3, u32 a) {
    asm volatile("ldmatrix.sync.aligned.m8n8.x4.shared.b16 {%0,%1,%2,%3}, [%4];"
                 : "=r"(r0), "=r"(r1), "=r"(r2), "=r"(r3) : "r"(a));
}
__device__ __forceinline__ void mma_bf16(float* c, const u32* a, const u32* b) {
    asm volatile(
        "mma.sync.aligned.m16n8k16.row.col.f32.bf16.bf16.f32 "
        "{%0,%1,%2,%3}, {%4,%5,%6,%7}, {%8,%9}, {%0,%1,%2,%3};"
        : "+f"(c[0]), "+f"(c[1]), "+f"(c[2]), "+f"(c[3])
        : "r"(a[0]), "r"(a[1]), "r"(a[2]), "r"(a[3]), "r"(b[0]), "r"(b[1]));
}

__device__ __forceinline__ float phi_act(float z) {
    return z > 0.f ? z + 2.f : __expf(z) + 1.f;
}
__device__ __forceinline__ void split1(float x, __nv_bfloat16& h, __nv_bfloat16& l) {
    h = __float2bfloat16(x);
    l = __float2bfloat16(x - __bfloat162float(h));
}
__device__ __forceinline__ u32 pack_bf2(__nv_bfloat16 a, __nv_bfloat16 b) {
    __nv_bfloat162 p; p.x = a; p.y = b;
    return *(u32*)&p;
}

// ---------------------------------------------------------------------------
// Core mainloop, 128 threads, warp grid 2x2, warp tile 64x64.
// acc[4][8][4]: i = m16 tile (0..3), jj = n8 tile (0..7).
// ---------------------------------------------------------------------------
__device__ __forceinline__ void run_gemm(
    char* sm, u32 smb,
    const __nv_bfloat16* __restrict__ Ah, const __nv_bfloat16* __restrict__ Al, long sA,
    const __nv_bfloat16* __restrict__ Bh, const __nv_bfloat16* __restrict__ Bl, long sB,
    int NB, float acc[4][8][4])
{
    const int tid = threadIdx.x, wid = tid >> 5, lane = tid & 31;
    const int warp_m = (wid & 1) * 64, warp_n = (wid >> 1) * 64;

    auto issue_stage = [&](int s, int kb) {
        u32 base = smb + s * STAGE_B;
#pragma unroll
        for (int i = 0; i < 16; i++) {
            int ch = i * 128 + tid;                // 2048 chunks of 16B
            int tile = ch >> 9, row = (ch >> 2) & 127, kc = ch & 3;
            const __nv_bfloat16* gb =
                (tile == 0) ? Ah : (tile == 1) ? Al : (tile == 2) ? Bh : Bl;
            long st = (tile < 2) ? sA : sB;
            cp_async16(base + tile * TILE_B + row * 80 + kc * 16,
                       gb + (long)row * st + (long)kb * 32 + kc * 8);
        }
        CP_COMMIT();
    };

    issue_stage(0, 0);

    for (int kb = 0; kb < NB; kb++) {
        if (kb + 1 < NB) { issue_stage((kb + 1) & 1, kb + 1); CP_WAIT(1); }
        else             { CP_WAIT(0); }
        __syncthreads();

        u32 sb = smb + (kb & 1) * STAGE_B;
        u32 aAddr = sb + (warp_m + (lane & 15)) * 80 + (lane >> 4) * 16;
        u32 bAddr = sb + 2 * TILE_B +
                    (warp_n + (lane & 7) + ((lane >> 4) << 3)) * 80 +
                    ((lane >> 3) & 1) * 16;

#pragma unroll
        for (int kh = 0; kh < 2; kh++) {
            u32 ah[4][4], al[4][4];
#pragma unroll
            for (int i = 0; i < 4; i++) {
                ldmx4(ah[i][0], ah[i][1], ah[i][2], ah[i][3],
                      aAddr + i * 16 * 80 + kh * 32);
                ldmx4(al[i][0], al[i][1], al[i][2], al[i][3],
                      aAddr + TILE_B + i * 16 * 80 + kh * 32);
            }
#pragma unroll
            for (int jh = 0; jh < 2; jh++) {
                u32 bh[4][2], bl[4][2];
                ldmx4(bh[0][0], bh[0][1], bh[1][0], bh[1][1],
                      bAddr + (jh * 2) * 16 * 80 + kh * 32);
                ldmx4(bh[2][0], bh[2][1], bh[3][0], bh[3][1],
                      bAddr + (jh * 2 + 1) * 16 * 80 + kh * 32);
                ldmx4(bl[0][0], bl[0][1], bl[1][0], bl[1][1],
                      bAddr + TILE_B + (jh * 2) * 16 * 80 + kh * 32);
                ldmx4(bl[2][0], bl[2][1], bl[3][0], bl[3][1],
                      bAddr + TILE_B + (jh * 2 + 1) * 16 * 80 + kh * 32);
#pragma unroll
                for (int i = 0; i < 4; i++)
#pragma unroll
                    for (int j = 0; j < 4; j++)
                        mma_bf16(acc[i][jh * 4 + j], ah[i], bh[j]);
#pragma unroll
                for (int i = 0; i < 4; i++)
#pragma unroll
                    for (int j = 0; j < 4; j++)
                        mma_bf16(acc[i][jh * 4 + j], ah[i], bl[j]);
#pragma unroll
                for (int i = 0; i < 4; i++)
#pragma unroll
                    for (int j = 0; j < 4; j++)
                        mma_bf16(acc[i][jh * 4 + j], al[i], bh[j]);
            }
        }
        __syncthreads();
    }
}

// Store per-warp accumulators into Cs[128][132] f32 (reuses stage memory).
__device__ __forceinline__ void stage_C(char* sm, float acc[4][8][4])
{
    const int tid = threadIdx.x, wid = tid >> 5, lane = tid & 31;
    const int warp_m = (wid & 1) * 64, warp_n = (wid >> 1) * 64;
    float* Cs = (float*)sm;
#pragma unroll
    for (int i = 0; i < 4; i++)
#pragma unroll
        for (int jj = 0; jj < 8; jj++) {
            int r = warp_m + i * 16 + (lane >> 2);
            int c = warp_n + jj * 8 + (lane & 3) * 2;
            *(float2*)&Cs[r * 132 + c] =
                make_float2(acc[i][jj][0], acc[i][jj][1]);
            *(float2*)&Cs[(r + 8) * 132 + c] =
                make_float2(acc[i][jj][2], acc[i][jj][3]);
        }
    __syncthreads();
}

#define ACC_DECL() float acc[4][8][4];                                   \
    _Pragma("unroll") for (int i = 0; i < 4; i++)                        \
    _Pragma("unroll") for (int j = 0; j < 8; j++)                        \
    _Pragma("unroll") for (int e = 0; e < 4; e++) acc[i][j][e] = 0.f;

// ---------------------------------------------------------------------------
// proj kernel (128 thr): blockIdx.x<256 -> K-projection, else Q-projection.
// ---------------------------------------------------------------------------
__global__ __launch_bounds__(128) void proj_kernel(
    const float* __restrict__ bk, const float* __restrict__ bq)
{
    extern __shared__ char sm[];
    u32 smb = smem_u32(sm);
    const int tid = threadIdx.x;
    const int b = blockIdx.y;
    const bool isK = blockIdx.x < 256;
    int c0, t0 = 0, r0 = 0;
    const __nv_bfloat16 *Ah, *Al, *Bh, *Bl;
    if (isK) {
        c0 = (blockIdx.x >> 7) * 128;
        t0 = (blockIdx.x & 127) * 128;
        Ah = g_WkTh + c0 * 256;  Al = g_WkTl + c0 * 256;
        Bh = g_Xh + ((long)b * 16384 + t0) * 256;
        Bl = g_Xl + ((long)b * 16384 + t0) * 256;
    } else {
        int xi = blockIdx.x - 256;
        r0 = (xi >> 1) * 128;
        c0 = (xi & 1) * 128;
        Ah = g_Xh + ((long)b * 16384 + r0) * 256;
        Al = g_Xl + ((long)b * 16384 + r0) * 256;
        Bh = g_WqTh + c0 * 256;  Bl = g_WqTl + c0 * 256;
    }

    ACC_DECL();
    run_gemm(sm, smb, Ah, Al, 256, Bh, Bl, 256, 8, acc);
    stage_C(sm, acc);
    const float* Cs = (const float*)sm;

    if (isK) {
        const int w0 = t0 >> 4;   // 8 windows in this token tile
#pragma unroll
        for (int it = 0; it < 16; it++) {
            int task = it * 128 + tid;            // 2048 = 128 c x 16 m
            int c = task >> 4, m = task & 15;
            float bias = bk[c0 + c];
            u32 H[4], L[4];
#pragma unroll
            for (int wl = 0; wl < 4; wl++) {
                float x0 = phi_act(Cs[c * 132 + (2 * wl) * 16 + m] + bias);
                float x1 = phi_act(Cs[c * 132 + (2 * wl + 1) * 16 + m] + bias);
                __nv_bfloat16 h0, l0, h1, l1;
                split1(x0, h0, l0); split1(x1, h1, l1);
                H[wl] = pack_bf2(h0, h1); L[wl] = pack_bf2(l0, l1);
            }
            long off = ((long)b * 256 + c0 + c) * 16384 + m * 1024 + w0;
            *(uint4*)(g_PKh + off) = make_uint4(H[0], H[1], H[2], H[3]);
            *(uint4*)(g_PKl + off) = make_uint4(L[0], L[1], L[2], L[3]);
        }
    } else {
#pragma unroll
        for (int it = 0; it < 16; it++) {
            int task = it * 128 + tid;            // 2048 = 128 r x 16 chunks
            int r = task >> 4, ch = task & 15;
            u32 H[4], L[4];
#pragma unroll
            for (int p = 0; p < 4; p++) {
                int col = ch * 8 + 2 * p;
                float x0 = phi_act(Cs[r * 132 + col] + bq[c0 + col]);
                float x1 = phi_act(Cs[r * 132 + col + 1] + bq[c0 + col + 1]);
                __nv_bfloat16 h0, l0, h1, l1;
                split1(x0, h0, l0); split1(x1, h1, l1);
                H[p] = pack_bf2(h0, h1); L[p] = pack_bf2(l0, l1);
            }
            long off = ((long)b * 1024 + r0 + r) * 256 + c0 + ch * 8;
            *(uint4*)(g_PQh + off) = make_uint4(H[0], H[1], H[2], H[3]);
            *(uint4*)(g_PQl + off) = make_uint4(L[0], L[1], L[2], L[3]);
        }
    }
}

// ---------------------------------------------------------------------------
// kv kernel (partial, 128 thr): one 256-token K-slice.
// grid (dtile=2, ctile=2, slice*32 + b*16 + m), NB=8. fp32 partial output.
// ---------------------------------------------------------------------------
__global__ __launch_bounds__(128) void kv_kernel()
{
    extern __shared__ char sm[];
    u32 smb = smem_u32(sm);
    const int tid = threadIdx.x;
    const int zz = blockIdx.z;
    const int slice = zz >> 5, bm = zz & 31;
    const int b = bm >> 4, m = bm & 15;
    const int d0 = blockIdx.x * 128, c0 = blockIdx.y * 128;
    const long abase = ((long)b * 256 + d0) * 16384 + m * 1024 + slice * 256;
    const long bbase = ((long)b * 256 + c0) * 16384 + m * 1024 + slice * 256;

    ACC_DECL();
    run_gemm(sm, smb, g_VTh + abase, g_VTl + abase, 16384,
             g_PKh + bbase, g_PKl + bbase, 16384, 8, acc);
    stage_C(sm, acc);
    const float* Cs = (const float*)sm;

    float* dstS = g_KVp + (long)slice * (2L * 4096 * 256);
#pragma unroll
    for (int it = 0; it < 16; it++) {
        int task = it * 128 + tid;                // 2048 = 128 d x 16 chunks
        int d = task >> 4, ch = task & 15;
        float* dst = dstS + ((long)b * 4096 + m * 256 + d0 + d) * 256 + c0 + ch * 8;
        *(float4*)(dst)     = *(const float4*)&Cs[d * 132 + ch * 8];
        *(float4*)(dst + 4) = *(const float4*)&Cs[d * 132 + ch * 8 + 4];
    }
}

// ---------------------------------------------------------------------------
// kv merge: sum 4 fp32 slices, split to bf16 hi/lo. 2M elements.
// ---------------------------------------------------------------------------
__global__ __launch_bounds__(256) void kv_merge_kernel()
{
    const long S = 2L * 4096 * 256;
    long i = (long)blockIdx.x * 256 + threadIdx.x;   // float4 index
    float4 a0 = ((const float4*)g_KVp)[i];
    float4 a1 = ((const float4*)(g_KVp + S))[i];
    float4 a2 = ((const float4*)(g_KVp + 2 * S))[i];
    float4 a3 = ((const float4*)(g_KVp + 3 * S))[i];
    float f[4] = { (a0.x + a1.x) + (a2.x + a3.x),
                   (a0.y + a1.y) + (a2.y + a3.y),
                   (a0.z + a1.z) + (a2.z + a3.z),
                   (a0.w + a1.w) + (a2.w + a3.w) };
    __nv_bfloat16 h0, l0, h1, l1, h2, l2, h3, l3;
    split1(f[0], h0, l0); split1(f[1], h1, l1);
    split1(f[2], h2, l2); split1(f[3], h3, l3);
    ((uint2*)g_KVh)[i] = make_uint2(pack_bf2(h0, h1), pack_bf2(h2, h3));
    ((uint2*)g_KVl)[i] = make_uint2(pack_bf2(l0, l1), pack_bf2(l2, l3));
}

// ---------------------------------------------------------------------------
// att kernel (128 thr): out[b][w*256+n*16+m][d] = R + p. K=256 (NB=8).
// ---------------------------------------------------------------------------
__global__ __launch_bounds__(128) void att_kernel(
    const float* __restrict__ embed, const float* __restrict__ Wp,
    const float* __restrict__ bp, float* __restrict__ out)
{
    extern __shared__ char sm[];
    u32 smb = smem_u32(sm);
    const int tid = threadIdx.x;
    const int b = blockIdx.z;
    const int r0 = blockIdx.x * 128;
    const int j0 = blockIdx.y * 128;
    const int m = j0 >> 8, d0 = j0 & 255;
    const long abase = ((long)b * 1024 + r0) * 256;
    const long bbase = ((long)b * 4096 + j0) * 256;

    {
        int r = r0 + tid, w = r >> 4, n = r & 15;
        const float* e = embed + ((((long)b * 1024 + w) * 16 + n) * 16 + m) * 3;
        ((float*)(sm + SM_PS))[tid] =
            e[0] * Wp[0] + e[1] * Wp[1] + e[2] * Wp[2] + bp[0];
    }

    ACC_DECL();
    run_gemm(sm, smb, g_PQh + abase, g_PQl + abase, 256,
             g_KVh + bbase, g_KVl + bbase, 256, 8, acc);
    stage_C(sm, acc);
    const float* Cs = (const float*)sm;

#pragma unroll
    for (int it = 0; it < 32; it++) {
        int task = it * 128 + tid;                // 4096 = 128 r x 32 f4-chunks
        int r = task >> 5, ch = task & 31;
        float4 v = *(const float4*)&Cs[r * 132 + ch * 4];
        float p = ((const float*)(sm + SM_PS))[r];
        v.x += p; v.y += p; v.z += p; v.w += p;
        int rg = r0 + r, w = rg >> 4, n = rg & 15;
        long t = (long)w * 256 + n * 16 + m;
        *(float4*)(out + ((long)b * 16384 + t) * 256 + d0 + ch * 4) = v;
    }
}

// ---------------------------------------------------------------------------
// prep kernels
// ---------------------------------------------------------------------------
__global__ __launch_bounds__(256) void prep_split(const float* __restrict__ X)
{
    long i = (long)blockIdx.x * 256 + threadIdx.x;   // float4 index
    float4 v = ((const float4*)X)[i];
    __nv_bfloat16 h0, l0, h1, l1, h2, l2, h3, l3;
    split1(v.x, h0, l0); split1(v.y, h1, l1);
    split1(v.z, h2, l2); split1(v.w, h3, l3);
    ((uint2*)g_Xh)[i] = make_uint2(pack_bf2(h0, h1), pack_bf2(h2, h3));
    ((uint2*)g_Xl)[i] = make_uint2(pack_bf2(l0, l1), pack_bf2(l2, l3));
}

// VT[b][d][m*1024+w] = X[b][w*16+m][d]; grid (wtile=32, dtile=8, b*16+m)
__global__ __launch_bounds__(256) void prep_vt(const float* __restrict__ X)
{
    __shared__ float tile[32][33];
    const int bm = blockIdx.z, b = bm >> 4, m = bm & 15;
    const int w0 = blockIdx.x * 32, d0 = blockIdx.y * 32;
    const int dx = threadIdx.x & 31, dy = threadIdx.x >> 5;
#pragma unroll
    for (int p = 0; p < 4; p++) {
        int w = w0 + dy + p * 8;
        tile[dy + p * 8][dx] =
            X[((long)b * 16384 + (long)w * 16 + m) * 256 + d0 + dx];
    }
    __syncthreads();
#pragma unroll
    for (int p = 0; p < 4; p++) {
        int d = d0 + dy + p * 8;
        float v = tile[dx][dy + p * 8];
        __nv_bfloat16 h, l; split1(v, h, l);
        long off = ((long)b * 256 + d) * 16384 + m * 1024 + w0 + dx;
        g_VTh[off] = h; g_VTl[off] = l;
    }
}

// WT[n][k] = W[k][n]; grid (ktile=8, ntile=8, 2: 0=Wk,1=Wq)
__global__ __launch_bounds__(256) void prep_w(
    const float* __restrict__ Wk, const float* __restrict__ Wq)
{
    __shared__ float tile[32][33];
    const int isQ = blockIdx.z;
    const float* W = isQ ? Wq : Wk;
    __nv_bfloat16* TH = isQ ? g_WqTh : g_WkTh;
    __nv_bfloat16* TL = isQ ? g_WqTl : g_WkTl;
    const int k0 = blockIdx.x * 32, n0 = blockIdx.y * 32;
    const int dx = threadIdx.x & 31, dy = threadIdx.x >> 5;
#pragma unroll
    for (int p = 0; p < 4; p++)
        tile[dy + p * 8][dx] = W[(k0 + dy + p * 8) * 256 + n0 + dx];
    __syncthreads();
#pragma unroll
    for (int p = 0; p < 4; p++) {
        float v = tile[dx][dy + p * 8];
        __nv_bfloat16 h, l; split1(v, h, l);
        int off = (n0 + dy + p * 8) * 256 + k0 + dx;
        TH[off] = h; TL[off] = l;
    }
}

// ---------------------------------------------------------------------------
// Inputs (metadata order): input, embed_qk, Wq, bq, Wk, bk, Wp, bp
// ---------------------------------------------------------------------------
extern "C" void kernel_launch(void* const* d_in, const int* in_sizes, int n_in,
                              void* d_out, int out_size)
{
    const float* input = (const float*)d_in[0];
    const float* embed = (const float*)d_in[1];
    const float* Wq    = (const float*)d_in[2];
    const float* bq    = (const float*)d_in[3];
    const float* Wk    = (const float*)d_in[4];
    const float* bk    = (const float*)d_in[5];
    const float* Wp    = (const float*)d_in[6];
    const float* bp    = (const float*)d_in[7];
    float* out = (float*)d_out;

    cudaFuncSetAttribute(proj_kernel, cudaFuncAttributeMaxDynamicSharedMemorySize, SMEM_BYTES);
    cudaFuncSetAttribute(kv_kernel,   cudaFuncAttributeMaxDynamicSharedMemorySize, SMEM_BYTES);
    cudaFuncSetAttribute(att_kernel,  cudaFuncAttributeMaxDynamicSharedMemorySize, SMEM_BYTES);

    prep_split<<<8192, 256>>>(input);
    prep_vt<<<dim3(32, 8, 32), 256>>>(input);
    prep_w<<<dim3(8, 8, 2), 256>>>(Wk, Wq);

    proj_kernel<<<dim3(272, 2), 128, SMEM_BYTES>>>(bk, bq);
    kv_kernel<<<dim3(2, 2, 128), 128, SMEM_BYTES>>>();
    kv_merge_kernel<<<2048, 256>>>();
    att_kernel<<<dim3(8, 32, 2), 128, SMEM_BYTES>>>(embed, Wp, bp, out);
}

// round 8
// speedup vs baseline: 1.2523x; 1.1380x over previous
#include <cuda_runtime.h>
#include <cuda_bf16.h>

// ---------------------------------------------------------------------------
// Round 8: exact R4 geometry (256 thr, 2x4 warp grid, 64x32 warp tiles,
// 2-stage cp.async, 2 CTAs/SM, plain kv) + crossbar-byte reduction:
//   * 64B-pitch XOR-swizzled smem tiles (no 80B padding: writes -20%)
//   * single __syncthreads per k-step (barriers halved)
// mma.sync.m16n8k16 bf16 split-hi/lo (hh+hl+lh). t' = m*1024 + w.
// ---------------------------------------------------------------------------

typedef unsigned int u32;

// ---------------- device buffers (bf16 hi/lo splits) -----------------------
__device__ __nv_bfloat16 g_Xh[2L * 16384 * 256], g_Xl[2L * 16384 * 256];
__device__ __nv_bfloat16 g_VTh[2L * 256 * 16384], g_VTl[2L * 256 * 16384];
__device__ __nv_bfloat16 g_WkTh[256 * 256], g_WkTl[256 * 256];
__device__ __nv_bfloat16 g_WqTh[256 * 256], g_WqTl[256 * 256];
__device__ __nv_bfloat16 g_PKh[2L * 256 * 16384], g_PKl[2L * 256 * 16384];
__device__ __nv_bfloat16 g_PQh[2L * 1024 * 256], g_PQl[2L * 1024 * 256];
__device__ __nv_bfloat16 g_KVh[2L * 4096 * 256], g_KVl[2L * 4096 * 256];

// ---------------- smem geometry -------------------------------------------
// One stage = 4 tiles (Ah, Al, Bh, Bl), each 128 rows x 64B, XOR-swizzled:
// phys = row*64 + ((chunk16 ^ ((row>>1)&3)) << 4).
#define TILE_B   8192                  // 128 * 64
#define STAGE_B  (4 * TILE_B)          // 32768
#define CS_BYTES (128 * 132 * 4)       // 67584 epilogue staging
#define SM_PS    67712                 // scratch after Cs
#define SMEM_BYTES (SM_PS + 1024)      // 68736 -> 2 CTAs/SM

// ---------------- PTX helpers ---------------------------------------------
__device__ __forceinline__ u32 smem_u32(const void* p) {
    u32 a;
    asm("{ .reg .u64 t; cvta.to.shared.u64 t, %1; cvt.u32.u64 %0, t; }"
        : "=r"(a) : "l"(p));
    return a;
}
__device__ __forceinline__ void cp_async16(u32 dst, const void* src) {
    asm volatile("cp.async.cg.shared.global [%0], [%1], 16;"
                 :: "r"(dst), "l"(src));
}
#define CP_COMMIT() asm volatile("cp.async.commit_group;" ::: "memory")
#define CP_WAIT(n)  asm volatile("cp.async.wait_group %0;" :: "n"(n) : "memory")

__device__ __forceinline__ void ldmx4(u32& r0, u32& r1, u32& r2, u32& r3, u32 a) {
    asm volatile("ldmatrix.sync.aligned.m8n8.x4.shared.b16 {%0,%1,%2,%3}, [%4];"
                 : "=r"(r0), "=r"(r1), "=r"(r2), "=r"(r3) : "r"(a));
}
__device__ __forceinline__ void mma_bf16(float* c, const u32* a, const u32* b) {
    asm volatile(
        "mma.sync.aligned.m16n8k16.row.col.f32.bf16.bf16.f32 "
        "{%0,%1,%2,%3}, {%4,%5,%6,%7}, {%8,%9}, {%0,%1,%2,%3};"
        : "+f"(c[0]), "+f"(c[1]), "+f"(c[2]), "+f"(c[3])
        : "r"(a[0]), "r"(a[1]), "r"(a[2]), "r"(a[3]), "r"(b[0]), "r"(b[1]));
}

__device__ __forceinline__ float phi_act(float z) {
    return z > 0.f ? z + 2.f : __expf(z) + 1.f;
}
__device__ __forceinline__ void split1(float x, __nv_bfloat16& h, __nv_bfloat16& l) {
    h = __float2bfloat16(x);
    l = __float2bfloat16(x - __bfloat162float(h));
}
__device__ __forceinline__ u32 pack_bf2(__nv_bfloat16 a, __nv_bfloat16 b) {
    __nv_bfloat162 p; p.x = a; p.y = b;
    return *(u32*)&p;
}
// swizzled in-tile byte offset for (row, chunk16)
__device__ __forceinline__ u32 swz(u32 row, u32 c) {
    return row * 64 + ((c ^ ((row >> 1) & 3)) << 4);
}

// ---------------------------------------------------------------------------
// Core mainloop: acc(128x128 f32, per-warp 64x32) += A(128xK) * B(128xK)^T
// split-bf16 3-term. K = NB*32. 2-stage buffer, ONE barrier per k-step.
// ---------------------------------------------------------------------------
__device__ __forceinline__ void run_gemm(
    char* sm, u32 smb,
    const __nv_bfloat16* __restrict__ Ah, const __nv_bfloat16* __restrict__ Al, long sA,
    const __nv_bfloat16* __restrict__ Bh, const __nv_bfloat16* __restrict__ Bl, long sB,
    int NB, float acc[4][4][4])
{
    const int tid = threadIdx.x, wid = tid >> 5, lane = tid & 31;
    const int warp_m = (wid & 1) * 64, warp_n = (wid >> 1) * 32;

    auto issue_stage = [&](int s, int kb) {
        u32 base = smb + s * STAGE_B;
#pragma unroll
        for (int i = 0; i < 8; i++) {
            int ch = i * 256 + tid;                // 2048 chunks of 16B
            int tile = ch >> 9;
            u32 row = (ch >> 2) & 127, kc = ch & 3;
            const __nv_bfloat16* gb =
                (tile == 0) ? Ah : (tile == 1) ? Al : (tile == 2) ? Bh : Bl;
            long st = (tile < 2) ? sA : sB;
            cp_async16(base + tile * TILE_B + swz(row, kc),
                       gb + (long)row * st + (long)kb * 32 + kc * 8);
        }
        CP_COMMIT();
    };

    // per-thread ldmatrix row/chunk decomposition
    const u32 arow = warp_m + (lane & 15);
    const u32 ac   = lane >> 4;                    // chunk bit0
    const u32 brow = warp_n + (lane & 7) + ((lane >> 4) << 3);
    const u32 bc   = (lane >> 3) & 1;

    issue_stage(0, 0);

    for (int kb = 0; kb < NB; kb++) {
        CP_WAIT(0);
        __syncthreads();
        if (kb + 1 < NB) issue_stage((kb + 1) & 1, kb + 1);

        u32 sb = smb + (kb & 1) * STAGE_B;

#pragma unroll
        for (int kh = 0; kh < 2; kh++) {
            u32 ah[4][4], al[4][4], bh[4][2], bl[4][2];
            const u32 aoff = swz(arow, ac + kh * 2);
            const u32 boff = swz(brow, bc + kh * 2);
#pragma unroll
            for (int i = 0; i < 4; i++) {
                ldmx4(ah[i][0], ah[i][1], ah[i][2], ah[i][3],
                      sb + aoff + i * 1024);
                ldmx4(al[i][0], al[i][1], al[i][2], al[i][3],
                      sb + TILE_B + aoff + i * 1024);
            }
#pragma unroll
            for (int j = 0; j < 2; j++) {
                ldmx4(bh[2 * j][0], bh[2 * j][1], bh[2 * j + 1][0], bh[2 * j + 1][1],
                      sb + 2 * TILE_B + boff + j * 1024);
                ldmx4(bl[2 * j][0], bl[2 * j][1], bl[2 * j + 1][0], bl[2 * j + 1][1],
                      sb + 3 * TILE_B + boff + j * 1024);
            }
#pragma unroll
            for (int i = 0; i < 4; i++)
#pragma unroll
                for (int j = 0; j < 4; j++) {
                    mma_bf16(acc[i][j], ah[i], bh[j]);
                    mma_bf16(acc[i][j], ah[i], bl[j]);
                    mma_bf16(acc[i][j], al[i], bh[j]);
                }
        }
    }
    __syncthreads();   // protect smem before epilogue staging reuses it
}

// Store per-warp accumulators into Cs[128][132] f32 (reuses stage memory).
__device__ __forceinline__ void stage_C(char* sm, float acc[4][4][4])
{
    const int tid = threadIdx.x, wid = tid >> 5, lane = tid & 31;
    const int warp_m = (wid & 1) * 64, warp_n = (wid >> 1) * 32;
    float* Cs = (float*)sm;
#pragma unroll
    for (int i = 0; i < 4; i++)
#pragma unroll
        for (int j = 0; j < 4; j++) {
            int r = warp_m + i * 16 + (lane >> 2);
            int c = warp_n + j * 8 + (lane & 3) * 2;
            *(float2*)&Cs[r * 132 + c] =
                make_float2(acc[i][j][0], acc[i][j][1]);
            *(float2*)&Cs[(r + 8) * 132 + c] =
                make_float2(acc[i][j][2], acc[i][j][3]);
        }
    __syncthreads();
}

#define ACC_DECL() float acc[4][4][4];                                   \
    _Pragma("unroll") for (int i = 0; i < 4; i++)                        \
    _Pragma("unroll") for (int j = 0; j < 4; j++)                        \
    _Pragma("unroll") for (int e = 0; e < 4; e++) acc[i][j][e] = 0.f;

// ---------------------------------------------------------------------------
// proj kernel: blockIdx.x<256 -> K-projection (M=c, N=tokens),
//              else            -> Q-projection (M=r, N=c).  K=256 (NB=8).
// ---------------------------------------------------------------------------
__global__ __launch_bounds__(256) void proj_kernel(
    const float* __restrict__ bk, const float* __restrict__ bq)
{
    extern __shared__ char sm[];
    u32 smb = smem_u32(sm);
    const int tid = threadIdx.x;
    const int b = blockIdx.y;
    const bool isK = blockIdx.x < 256;
    int c0, t0 = 0, r0 = 0;
    const __nv_bfloat16 *Ah, *Al, *Bh, *Bl;
    if (isK) {
        c0 = (blockIdx.x >> 7) * 128;
        t0 = (blockIdx.x & 127) * 128;
        Ah = g_WkTh + c0 * 256;  Al = g_WkTl + c0 * 256;
        Bh = g_Xh + ((long)b * 16384 + t0) * 256;
        Bl = g_Xl + ((long)b * 16384 + t0) * 256;
    } else {
        int xi = blockIdx.x - 256;
        r0 = (xi >> 1) * 128;
        c0 = (xi & 1) * 128;
        Ah = g_Xh + ((long)b * 16384 + r0) * 256;
        Al = g_Xl + ((long)b * 16384 + r0) * 256;
        Bh = g_WqTh + c0 * 256;  Bl = g_WqTl + c0 * 256;
    }

    ACC_DECL();
    run_gemm(sm, smb, Ah, Al, 256, Bh, Bl, 256, 8, acc);
    stage_C(sm, acc);
    const float* Cs = (const float*)sm;

    if (isK) {
        const int w0 = t0 >> 4;   // 8 windows in this token tile
#pragma unroll
        for (int it = 0; it < 8; it++) {
            int task = it * 256 + tid;            // 2048 = 128 c x 16 m
            int c = task >> 4, m = task & 15;
            float bias = bk[c0 + c];
            u32 H[4], L[4];
#pragma unroll
            for (int wl = 0; wl < 4; wl++) {
                float x0 = phi_act(Cs[c * 132 + (2 * wl) * 16 + m] + bias);
                float x1 = phi_act(Cs[c * 132 + (2 * wl + 1) * 16 + m] + bias);
                __nv_bfloat16 h0, l0, h1, l1;
                split1(x0, h0, l0); split1(x1, h1, l1);
                H[wl] = pack_bf2(h0, h1); L[wl] = pack_bf2(l0, l1);
            }
            long off = ((long)b * 256 + c0 + c) * 16384 + m * 1024 + w0;
            *(uint4*)(g_PKh + off) = make_uint4(H[0], H[1], H[2], H[3]);
            *(uint4*)(g_PKl + off) = make_uint4(L[0], L[1], L[2], L[3]);
        }
    } else {
#pragma unroll
        for (int it = 0; it < 8; it++) {
            int task = it * 256 + tid;            // 2048 = 128 r x 16 chunks
            int r = task >> 4, ch = task & 15;
            u32 H[4], L[4];
#pragma unroll
            for (int p = 0; p < 4; p++) {
                int col = ch * 8 + 2 * p;
                float x0 = phi_act(Cs[r * 132 + col] + bq[c0 + col]);
                float x1 = phi_act(Cs[r * 132 + col + 1] + bq[c0 + col + 1]);
                __nv_bfloat16 h0, l0, h1, l1;
                split1(x0, h0, l0); split1(x1, h1, l1);
                H[p] = pack_bf2(h0, h1); L[p] = pack_bf2(l0, l1);
            }
            long off = ((long)b * 1024 + r0 + r) * 256 + c0 + ch * 8;
            *(uint4*)(g_PQh + off) = make_uint4(H[0], H[1], H[2], H[3]);
            *(uint4*)(g_PQl + off) = make_uint4(L[0], L[1], L[2], L[3]);
        }
    }
}

// ---------------------------------------------------------------------------
// kv kernel: KVT[b][m*256+d][c] = sum_{t'} VT[d][t'] phiKT[c][t'], K=1024.
// grid (dtile=2, ctile=2, b*16+m), NB=32.
// ---------------------------------------------------------------------------
__global__ __launch_bounds__(256) void kv_kernel()
{
    extern __shared__ char sm[];
    u32 smb = smem_u32(sm);
    const int tid = threadIdx.x;
    const int bm = blockIdx.z, b = bm >> 4, m = bm & 15;
    const int d0 = blockIdx.x * 128, c0 = blockIdx.y * 128;
    const long abase = ((long)b * 256 + d0) * 16384 + m * 1024;
    const long bbase = ((long)b * 256 + c0) * 16384 + m * 1024;

    ACC_DECL();
    run_gemm(sm, smb, g_VTh + abase, g_VTl + abase, 16384,
             g_PKh + bbase, g_PKl + bbase, 16384, 32, acc);
    stage_C(sm, acc);
    const float* Cs = (const float*)sm;

#pragma unroll
    for (int it = 0; it < 8; it++) {
        int task = it * 256 + tid;                // 2048 = 128 d x 16 chunks
        int d = task >> 4, ch = task & 15;
        u32 H[4], L[4];
#pragma unroll
        for (int p = 0; p < 4; p++) {
            float x0 = Cs[d * 132 + ch * 8 + 2 * p];
            float x1 = Cs[d * 132 + ch * 8 + 2 * p + 1];
            __nv_bfloat16 h0, l0, h1, l1;
            split1(x0, h0, l0); split1(x1, h1, l1);
            H[p] = pack_bf2(h0, h1); L[p] = pack_bf2(l0, l1);
        }
        long off = ((long)b * 4096 + m * 256 + d0 + d) * 256 + c0 + ch * 8;
        *(uint4*)(g_KVh + off) = make_uint4(H[0], H[1], H[2], H[3]);
        *(uint4*)(g_KVl + off) = make_uint4(L[0], L[1], L[2], L[3]);
    }
}

// ---------------------------------------------------------------------------
// att kernel: out[b][w*256+n*16+m][d] = sum_c phiQ[r][c] KVT[m*256+d][c] + p.
// grid (rtile=8, jtile=32, b). K=256 (NB=8).
// ---------------------------------------------------------------------------
__global__ __launch_bounds__(256) void att_kernel(
    const float* __restrict__ embed, const float* __restrict__ Wp,
    const float* __restrict__ bp, float* __restrict__ out)
{
    extern __shared__ char sm[];
    u32 smb = smem_u32(sm);
    const int tid = threadIdx.x;
    const int b = blockIdx.z;
    const int r0 = blockIdx.x * 128;
    const int j0 = blockIdx.y * 128;
    const int m = j0 >> 8, d0 = j0 & 255;
    const long abase = ((long)b * 1024 + r0) * 256;
    const long bbase = ((long)b * 4096 + j0) * 256;

    if (tid < 128) {
        int r = r0 + tid, w = r >> 4, n = r & 15;
        const float* e = embed + ((((long)b * 1024 + w) * 16 + n) * 16 + m) * 3;
        ((float*)(sm + SM_PS))[tid] =
            e[0] * Wp[0] + e[1] * Wp[1] + e[2] * Wp[2] + bp[0];
    }

    ACC_DECL();
    run_gemm(sm, smb, g_PQh + abase, g_PQl + abase, 256,
             g_KVh + bbase, g_KVl + bbase, 256, 8, acc);
    stage_C(sm, acc);
    const float* Cs = (const float*)sm;

#pragma unroll
    for (int it = 0; it < 16; it++) {
        int task = it * 256 + tid;                // 4096 = 128 r x 32 f4-chunks
        int r = task >> 5, ch = task & 31;
        float4 v = *(const float4*)&Cs[r * 132 + ch * 4];
        float p = ((const float*)(sm + SM_PS))[r];
        v.x += p; v.y += p; v.z += p; v.w += p;
        int rg = r0 + r, w = rg >> 4, n = rg & 15;
        long t = (long)w * 256 + n * 16 + m;
        *(float4*)(out + ((long)b * 16384 + t) * 256 + d0 + ch * 4) = v;
    }
}

// ---------------------------------------------------------------------------
// prep kernels
// ---------------------------------------------------------------------------
__global__ __launch_bounds__(256) void prep_split(const float* __restrict__ X)
{
    long i = (long)blockIdx.x * 256 + threadIdx.x;   // float4 index
    float4 v = ((const float4*)X)[i];
    __nv_bfloat16 h0, l0, h1, l1, h2, l2, h3, l3;
    split1(v.x, h0, l0); split1(v.y, h1, l1);
    split1(v.z, h2, l2); split1(v.w, h3, l3);
    ((uint2*)g_Xh)[i] = make_uint2(pack_bf2(h0, h1), pack_bf2(h2, h3));
    ((uint2*)g_Xl)[i] = make_uint2(pack_bf2(l0, l1), pack_bf2(l2, l3));
}

// VT[b][d][m*1024+w] = X[b][w*16+m][d]; grid (wtile=32, dtile=8, b*16+m)
__global__ __launch_bounds__(256) void prep_vt(const float* __restrict__ X)
{
    __shared__ float tile[32][33];
    const int bm = blockIdx.z, b = bm >> 4, m = bm & 15;
    const int w0 = blockIdx.x * 32, d0 = blockIdx.y * 32;
    const int dx = threadIdx.x & 31, dy = threadIdx.x >> 5;
#pragma unroll
    for (int p = 0; p < 4; p++) {
        int w = w0 + dy + p * 8;
        tile[dy + p * 8][dx] =
            X[((long)b * 16384 + (long)w * 16 + m) * 256 + d0 + dx];
    }
    __syncthreads();
#pragma unroll
    for (int p = 0; p < 4; p++) {
        int d = d0 + dy + p * 8;
        float v = tile[dx][dy + p * 8];
        __nv_bfloat16 h, l; split1(v, h, l);
        long off = ((long)b * 256 + d) * 16384 + m * 1024 + w0 + dx;
        g_VTh[off] = h; g_VTl[off] = l;
    }
}

// WT[n][k] = W[k][n]; grid (ktile=8, ntile=8, 2: 0=Wk,1=Wq)
__global__ __launch_bounds__(256) void prep_w(
    const float* __restrict__ Wk, const float* __restrict__ Wq)
{
    __shared__ float tile[32][33];
    const int isQ = blockIdx.z;
    const float* W = isQ ? Wq : Wk;
    __nv_bfloat16* TH = isQ ? g_WqTh : g_WkTh;
    __nv_bfloat16* TL = isQ ? g_WqTl : g_WkTl;
    const int k0 = blockIdx.x * 32, n0 = blockIdx.y * 32;
    const int dx = threadIdx.x & 31, dy = threadIdx.x >> 5;
#pragma unroll
    for (int p = 0; p < 4; p++)
        tile[dy + p * 8][dx] = W[(k0 + dy + p * 8) * 256 + n0 + dx];
    __syncthreads();
#pragma unroll
    for (int p = 0; p < 4; p++) {
        float v = tile[dx][dy + p * 8];
        __nv_bfloat16 h, l; split1(v, h, l);
        int off = (n0 + dy + p * 8) * 256 + k0 + dx;
        TH[off] = h; TL[off] = l;
    }
}

// ---------------------------------------------------------------------------
// Inputs (metadata order): input, embed_qk, Wq, bq, Wk, bk, Wp, bp
// ---------------------------------------------------------------------------
extern "C" void kernel_launch(void* const* d_in, const int* in_sizes, int n_in,
                              void* d_out, int out_size)
{
    const float* input = (const float*)d_in[0];
    const float* embed = (const float*)d_in[1];
    const float* Wq    = (const float*)d_in[2];
    const float* bq    = (const float*)d_in[3];
    const float* Wk    = (const float*)d_in[4];
    const float* bk    = (const float*)d_in[5];
    const float* Wp    = (const float*)d_in[6];
    const float* bp    = (const float*)d_in[7];
    float* out = (float*)d_out;

    cudaFuncSetAttribute(proj_kernel, cudaFuncAttributeMaxDynamicSharedMemorySize, SMEM_BYTES);
    cudaFuncSetAttribute(kv_kernel,   cudaFuncAttributeMaxDynamicSharedMemorySize, SMEM_BYTES);
    cudaFuncSetAttribute(att_kernel,  cudaFuncAttributeMaxDynamicSharedMemorySize, SMEM_BYTES);

    prep_split<<<8192, 256>>>(input);
    prep_vt<<<dim3(32, 8, 32), 256>>>(input);
    prep_w<<<dim3(8, 8, 2), 256>>>(Wk, Wq);

    proj_kernel<<<dim3(272, 2), 256, SMEM_BYTES>>>(bk, bq);
    kv_kernel<<<dim3(2, 2, 32), 256, SMEM_BYTES>>>();
    att_kernel<<<dim3(8, 32, 2), 256, SMEM_BYTES>>>(embed, Wp, bp, out);
}